// round 16
// baseline (speedup 1.0000x reference)
#include <cuda_runtime.h>
#include <cuda_bf16.h>
#include <math.h>
#include <stdint.h>

// Problem constants (shapes fixed by the dataset)
#define NN 100000           // nodes
#define NE 1000000          // edges
#define ET 4                // edge types
#define DI 64               // input dim
#define DH 256              // hidden dim
#define KU (ET*DI)          // 256 = update row width
#define G3 (3*DI)           // 192 = gate width
#define NSEG (NN*ET)        // 400000 segments
#define CAP 16              // edges per segment capacity (one 128B line; overflow handled)

// Scratch (device globals — allocation-free)
__device__ float g_update[(size_t)NN * KU];   // 102.4 MB
__device__ float g_hidden[(size_t)NN * DH];   // 102.4 MB
__device__ float g_gi[(size_t)NN * G3];       // 76.8 MB (edge lists pre-GEMM2: 400k*16*8B = 51.2MB)
__device__ float g_gh[(size_t)NN * G3];       // 76.8 MB (first 1.6MB = counts)
__device__ int   g_src[NE];                   // overflow-only
__device__ int   g_dst[NE];                   // overflow-only
__device__ int   g_typ[NE];                   // overflow-only
__device__ int   g_pos[NE];                   // overflow-only (read iff g_ovf)
__device__ int   g_is_i32;                    // 1 => edge arrays are int32
__device__ int   g_ovf;                       // 1 => at least one overflow edge

// Pre-rounded (tf32) weight copies
#define WOFF_MLP 0
#define WOFF_IH  (DH*KU)                   // 65536
#define WOFF_HH  (WOFF_IH + G3*DH)         // 114688
#define WTOTAL   (WOFF_HH + G3*DI)         // 126976
__device__ float g_wbuf[WTOTAL];

// ---------------------------------------------------------------------------
// tf32 helpers
// ---------------------------------------------------------------------------
__device__ __forceinline__ uint32_t to_tf32(float v) {
    uint32_t u;
    asm("cvt.rna.tf32.f32 %0, %1;" : "=r"(u) : "f"(v));
    return u;
}

__device__ __forceinline__ uint32_t smem_u32(const void* p) {
    return (uint32_t)__cvta_generic_to_shared(p);
}

// ---------------------------------------------------------------------------
// init: zero the segment counters + reset flags
// ---------------------------------------------------------------------------
__global__ void init_kernel(int* __restrict__ cnt) {
    int i = blockIdx.x * blockDim.x + threadIdx.x;
    if (i < NSEG) cnt[i] = 0;
    if (i == 0) { g_is_i32 = 0; g_ovf = 0; }
}

__global__ void probe_kernel(const long long* __restrict__ eidx) {
    int i = blockIdx.x * blockDim.x + threadIdx.x;   // 4096 probes
    long long v = eidx[i];
    if (v < 0 || v >= (long long)NN) atomicExch(&g_is_i32, 1);
}

// ---------------------------------------------------------------------------
// Fused convert+fill (known good from R14)
// ---------------------------------------------------------------------------
__global__ void fill_kernel(const void* __restrict__ eidx,
                            const void* __restrict__ etype,
                            const float* __restrict__ ew,
                            int* __restrict__ cnt,
                            unsigned long long* __restrict__ list) {
    int e = blockIdx.x * blockDim.x + threadIdx.x;
    if (e >= NE) return;
    int src, dst, t;
    if (g_is_i32) {
        const int* p = (const int*)eidx;
        src = p[e];
        dst = p[NE + e];
        t   = ((const int*)etype)[e];
    } else {
        const long long* p = (const long long*)eidx;
        src = (int)p[e];
        dst = (int)p[NE + e];
        t   = (int)((const long long*)etype)[e];
    }
    if ((unsigned)dst >= NN || (unsigned)t >= ET || (unsigned)src >= NN) return;
    int slot = dst * ET + t;
    int pos = atomicAdd(&cnt[slot], 1);
    if (pos < CAP) {
        unsigned long long pk =
            (unsigned long long)(unsigned)src |
            ((unsigned long long)__float_as_uint(ew[e]) << 32);
        list[(size_t)slot * CAP + pos] = pk;
    } else {                          // overflow: record for fallback
        g_pos[e] = pos;
        g_src[e] = src;
        g_dst[e] = dst;
        g_typ[e] = t;
        atomicExch(&g_ovf, 1);
    }
}

__global__ void round_weights_kernel(const float* __restrict__ mlpW,
                                     const float* __restrict__ wih,
                                     const float* __restrict__ whh) {
    int i = blockIdx.x * blockDim.x + threadIdx.x;
    if (i >= WTOTAL) return;
    float v;
    if (i < WOFF_IH)       v = mlpW[i];
    else if (i < WOFF_HH)  v = wih[i - WOFF_IH];
    else                   v = whh[i - WOFF_HH];
    g_wbuf[i] = __uint_as_float(to_tf32(v));
}

// ---------------------------------------------------------------------------
// gather: 4 threads/segment, each owns 16 consecutive floats (4x float4).
// Each thread prefetches 4 list entries (4x4 = CAP); entry j is broadcast
// with one width-4 shuffle. Halves shuffle/bookkeeping issues vs 8-thr/seg
// and doubles per-thread LDG ILP at identical x traffic.
// Output rounded rna->tf32 so GEMM1 skips its A-side cvt.
// ---------------------------------------------------------------------------
__global__ void gather_kernel(const float* __restrict__ x,
                              const int* __restrict__ cnt,
                              const unsigned long long* __restrict__ list,
                              float* __restrict__ upd) {
    int i = blockIdx.x * blockDim.x + threadIdx.x;   // NSEG*4 work items
    int seg = i >> 2;
    int t4  = i & 3;
    int c   = t4 * 16;         // float offset within the 64-wide row
    if (seg >= NSEG) return;
    int n = cnt[seg];
    if (n > CAP) n = CAP;
    const unsigned long long* lp = list + (size_t)seg * CAP;
    // group-cooperative list fetch (entries >= n are garbage, never used)
    unsigned long long e0 = lp[t4];
    unsigned long long e1 = lp[t4 + 4];
    unsigned long long e2 = lp[t4 + 8];
    unsigned long long e3 = lp[t4 + 12];
    float4 a0 = make_float4(0.f, 0.f, 0.f, 0.f);
    float4 a1 = make_float4(0.f, 0.f, 0.f, 0.f);
    float4 a2 = make_float4(0.f, 0.f, 0.f, 0.f);
    float4 a3 = make_float4(0.f, 0.f, 0.f, 0.f);
    for (int j = 0; j < n; j++) {
        unsigned long long sel;
        if (j < 4)       sel = e0;
        else if (j < 8)  sel = e1;
        else if (j < 12) sel = e2;
        else             sel = e3;
        unsigned long long pk = __shfl_sync(0xffffffffu, sel, j & 3, 4);
        int   src = (int)(unsigned)(pk & 0xffffffffull);
        float w   = __uint_as_float((uint32_t)(pk >> 32));
        if ((unsigned)src < NN) {
            const float* xr = x + (size_t)src * DI + c;
            float4 v0 = *(const float4*)(xr);
            float4 v1 = *(const float4*)(xr + 4);
            float4 v2 = *(const float4*)(xr + 8);
            float4 v3 = *(const float4*)(xr + 12);
            a0.x += w * v0.x; a0.y += w * v0.y; a0.z += w * v0.z; a0.w += w * v0.w;
            a1.x += w * v1.x; a1.y += w * v1.y; a1.z += w * v1.z; a1.w += w * v1.w;
            a2.x += w * v2.x; a2.y += w * v2.y; a2.z += w * v2.z; a2.w += w * v2.w;
            a3.x += w * v3.x; a3.y += w * v3.y; a3.z += w * v3.z; a3.w += w * v3.w;
        }
    }
    a0.x = __uint_as_float(to_tf32(a0.x)); a0.y = __uint_as_float(to_tf32(a0.y));
    a0.z = __uint_as_float(to_tf32(a0.z)); a0.w = __uint_as_float(to_tf32(a0.w));
    a1.x = __uint_as_float(to_tf32(a1.x)); a1.y = __uint_as_float(to_tf32(a1.y));
    a1.z = __uint_as_float(to_tf32(a1.z)); a1.w = __uint_as_float(to_tf32(a1.w));
    a2.x = __uint_as_float(to_tf32(a2.x)); a2.y = __uint_as_float(to_tf32(a2.y));
    a2.z = __uint_as_float(to_tf32(a2.z)); a2.w = __uint_as_float(to_tf32(a2.w));
    a3.x = __uint_as_float(to_tf32(a3.x)); a3.y = __uint_as_float(to_tf32(a3.y));
    a3.z = __uint_as_float(to_tf32(a3.z)); a3.w = __uint_as_float(to_tf32(a3.w));
    float* ur = upd + (size_t)seg * DI + c;
    *(float4*)(ur)      = a0;
    *(float4*)(ur + 4)  = a1;
    *(float4*)(ur + 8)  = a2;
    *(float4*)(ur + 12) = a3;
}

// Overflow edges (essentially never) — whole grid exits on one flag load.
__global__ void fallback_kernel(const float* __restrict__ x,
                                const float* __restrict__ ew,
                                float* __restrict__ upd) {
    if (!g_ovf) return;
    int e = blockIdx.x * blockDim.x + threadIdx.x;
    if (e >= NE) return;
    if (g_pos[e] < CAP) return;
    int src = g_src[e];
    int dst = g_dst[e];
    int t   = g_typ[e];
    if ((unsigned)src >= NN || (unsigned)dst >= NN || (unsigned)t >= ET) return;
    float w = ew[e];
    float* drow = upd + ((size_t)dst * ET + t) * DI;
    for (int c = 0; c < 16; c++) {
        float4 v = *(const float4*)(x + (size_t)src * DI + c * 4);
        float p0 = __uint_as_float(to_tf32(w * v.x));
        float p1 = __uint_as_float(to_tf32(w * v.y));
        float p2 = __uint_as_float(to_tf32(w * v.z));
        float p3 = __uint_as_float(to_tf32(w * v.w));
        asm volatile("red.global.add.v4.f32 [%0], {%1,%2,%3,%4};"
                     :: "l"(drow + c * 4), "f"(p0), "f"(p1), "f"(p2), "f"(p3)
                     : "memory");
    }
}

// ---------------------------------------------------------------------------
// TF32 mma.sync GEMM, BK=32, 3-stage cp.async (known good)
// ---------------------------------------------------------------------------
#define MMA_TF32(d, a, b0, b1)                                                 \
    asm volatile(                                                              \
        "mma.sync.aligned.m16n8k8.row.col.f32.tf32.tf32.f32 "                  \
        "{%0,%1,%2,%3},{%4,%5,%6,%7},{%8,%9},{%0,%1,%2,%3};"                   \
        : "+f"((d)[0]), "+f"((d)[1]), "+f"((d)[2]), "+f"((d)[3])               \
        : "r"((a)[0]), "r"((a)[1]), "r"((a)[2]), "r"((a)[3]),                  \
          "r"(b0), "r"(b1))

template<int K, int RELU, int CVT_A, int CVT_OUT>
__global__ void __launch_bounds__(256) gemm_tf32(const float* __restrict__ A,
                                                 const float* __restrict__ B,
                                                 const float* __restrict__ bias,
                                                 float* __restrict__ C,
                                                 int M, int N) {
    __shared__ float As[3][128][36];
    __shared__ float Bs[3][64][36];

    const int tid  = threadIdx.x;
    const int lane = tid & 31;
    const int w    = tid >> 5;
    const int wm   = (w & 3) * 32;
    const int wn   = (w >> 2) * 32;
    const int m0   = blockIdx.x * 128;
    const int n0   = blockIdx.y * 64;

    const int lrow = tid >> 3;
    const int lcol = (tid & 7) * 4;

    const int niter = K / 32;

    auto issue_tile = [&](int it, int s) {
        int k0 = it * 32;
#pragma unroll
        for (int p = 0; p < 4; p++) {
            int r  = p * 32 + lrow;
            int gm = m0 + r;
            const float* src = A + (size_t)gm * K + k0 + lcol;
            uint32_t dst = smem_u32(&As[s][r][lcol]);
            int sz = (gm < M) ? 16 : 0;
            asm volatile("cp.async.cg.shared.global [%0], [%1], 16, %2;"
                         :: "r"(dst), "l"(src), "r"(sz));
        }
#pragma unroll
        for (int p = 0; p < 2; p++) {
            int r = p * 32 + lrow;
            const float* src = B + (size_t)(n0 + r) * K + k0 + lcol;
            uint32_t dst = smem_u32(&Bs[s][r][lcol]);
            asm volatile("cp.async.cg.shared.global [%0], [%1], 16;"
                         :: "r"(dst), "l"(src));
        }
    };

    float acc[2][4][4];
#pragma unroll
    for (int mt = 0; mt < 2; mt++)
#pragma unroll
        for (int nt = 0; nt < 4; nt++)
#pragma unroll
            for (int j = 0; j < 4; j++) acc[mt][nt][j] = 0.f;

    issue_tile(0, 0);
    asm volatile("cp.async.commit_group;");
    if (niter > 1) issue_tile(1, 1);
    asm volatile("cp.async.commit_group;");

    int s = 0, s2 = 2;
    for (int i = 0; i < niter; i++) {
        asm volatile("cp.async.wait_group 1;");
        __syncthreads();

        if (i + 2 < niter) issue_tile(i + 2, s2);
        asm volatile("cp.async.commit_group;");

#pragma unroll
        for (int ks = 0; ks < 32; ks += 8) {
            uint32_t af[2][4];
#pragma unroll
            for (int mt = 0; mt < 2; mt++) {
                int r = wm + mt * 16 + (lane >> 2);
                int c = ks + (lane & 3);
                if (CVT_A) {
                    af[mt][0] = to_tf32(As[s][r][c]);
                    af[mt][1] = to_tf32(As[s][r + 8][c]);
                    af[mt][2] = to_tf32(As[s][r][c + 4]);
                    af[mt][3] = to_tf32(As[s][r + 8][c + 4]);
                } else {
                    af[mt][0] = __float_as_uint(As[s][r][c]);
                    af[mt][1] = __float_as_uint(As[s][r + 8][c]);
                    af[mt][2] = __float_as_uint(As[s][r][c + 4]);
                    af[mt][3] = __float_as_uint(As[s][r + 8][c + 4]);
                }
            }
#pragma unroll
            for (int nt = 0; nt < 4; nt++) {
                int cn = wn + nt * 8 + (lane >> 2);
                int ck = ks + (lane & 3);
                uint32_t b0 = __float_as_uint(Bs[s][cn][ck]);
                uint32_t b1 = __float_as_uint(Bs[s][cn][ck + 4]);
                MMA_TF32(acc[0][nt], af[0], b0, b1);
                MMA_TF32(acc[1][nt], af[1], b0, b1);
            }
        }
        s  = (s  == 2) ? 0 : s  + 1;
        s2 = (s2 == 2) ? 0 : s2 + 1;
    }

#pragma unroll
    for (int mt = 0; mt < 2; mt++) {
#pragma unroll
        for (int nt = 0; nt < 4; nt++) {
            int row = m0 + wm + mt * 16 + (lane >> 2);
            int col = n0 + wn + nt * 8 + 2 * (lane & 3);
            float b0v = bias[col];
            float b1v = bias[col + 1];
            float v0 = acc[mt][nt][0] + b0v;
            float v1 = acc[mt][nt][1] + b1v;
            float v2 = acc[mt][nt][2] + b0v;
            float v3 = acc[mt][nt][3] + b1v;
            if (RELU) {
                v0 = fmaxf(v0, 0.f); v1 = fmaxf(v1, 0.f);
                v2 = fmaxf(v2, 0.f); v3 = fmaxf(v3, 0.f);
            }
            if (CVT_OUT) {
                v0 = __uint_as_float(to_tf32(v0));
                v1 = __uint_as_float(to_tf32(v1));
                v2 = __uint_as_float(to_tf32(v2));
                v3 = __uint_as_float(to_tf32(v3));
            }
            if (row < M)
                *(float2*)(C + (size_t)row * N + col) = make_float2(v0, v1);
            if (row + 8 < M)
                *(float2*)(C + (size_t)(row + 8) * N + col) = make_float2(v2, v3);
        }
    }
}

// ---------------------------------------------------------------------------
// GRU gate epilogue, vectorized (known good)
// ---------------------------------------------------------------------------
__global__ void gates_kernel(const float* __restrict__ x,
                             const float* __restrict__ gi,
                             const float* __restrict__ gh,
                             float* __restrict__ out) {
    int i = blockIdx.x * blockDim.x + threadIdx.x;   // NN*16 work items
    if (i >= NN * 16) return;
    int m = i >> 4;
    int c = (i & 15) * 4;
    const float* gim = gi + (size_t)m * G3;
    const float* ghm = gh + (size_t)m * G3;
    float4 ir  = *(const float4*)(gim + c);
    float4 iz  = *(const float4*)(gim + 64 + c);
    float4 in_ = *(const float4*)(gim + 128 + c);
    float4 hr  = *(const float4*)(ghm + c);
    float4 hz  = *(const float4*)(ghm + 64 + c);
    float4 hn  = *(const float4*)(ghm + 128 + c);
    float4 hv  = *(const float4*)(x + (size_t)m * DI + c);
    float4 o;
    {
        float r = 1.f / (1.f + expf(-(ir.x + hr.x)));
        float z = 1.f / (1.f + expf(-(iz.x + hz.x)));
        float n = tanhf(in_.x + r * hn.x);
        o.x = (1.f - z) * n + z * hv.x;
    }
    {
        float r = 1.f / (1.f + expf(-(ir.y + hr.y)));
        float z = 1.f / (1.f + expf(-(iz.y + hz.y)));
        float n = tanhf(in_.y + r * hn.y);
        o.y = (1.f - z) * n + z * hv.y;
    }
    {
        float r = 1.f / (1.f + expf(-(ir.z + hr.z)));
        float z = 1.f / (1.f + expf(-(iz.z + hz.z)));
        float n = tanhf(in_.z + r * hn.z);
        o.z = (1.f - z) * n + z * hv.z;
    }
    {
        float r = 1.f / (1.f + expf(-(ir.w + hr.w)));
        float z = 1.f / (1.f + expf(-(iz.w + hz.w)));
        float n = tanhf(in_.w + r * hn.w);
        o.w = (1.f - z) * n + z * hv.w;
    }
    *(float4*)(out + (size_t)m * DI + c) = o;
}

// ---------------------------------------------------------------------------
// Launch
// ---------------------------------------------------------------------------
extern "C" void kernel_launch(void* const* d_in, const int* in_sizes, int n_in,
                              void* d_out, int out_size) {
    const float* x     = (const float*)d_in[0];      // [NN, 64]
    const void*  eidx  = d_in[1];                    // [2, NE] int32 or int64
    const void*  etype = d_in[2];                    // [NE]
    const float* ew    = (const float*)d_in[3];      // [NE]
    const float* mlpW  = (const float*)d_in[4];      // [256, 256]
    const float* mlpb  = (const float*)d_in[5];      // [256]
    const float* wih   = (const float*)d_in[6];      // [192, 256]
    const float* whh   = (const float*)d_in[7];      // [192, 64]
    const float* bih   = (const float*)d_in[8];      // [192]
    const float* bhh   = (const float*)d_in[9];      // [192]
    float*       out   = (float*)d_out;              // [NN, 64]

    float *upd, *hid, *gi, *gh, *wbuf;
    cudaGetSymbolAddress((void**)&upd, g_update);
    cudaGetSymbolAddress((void**)&hid, g_hidden);
    cudaGetSymbolAddress((void**)&gi,  g_gi);
    cudaGetSymbolAddress((void**)&gh,  g_gh);
    cudaGetSymbolAddress((void**)&wbuf, g_wbuf);

    int* cnt = (int*)gh;                                // 1.6MB of g_gh
    unsigned long long* list = (unsigned long long*)gi; // 51.2MB of g_gi

    const int MB128 = (NN + 127) / 128;   // 782

    // 0) init counters+flags, dtype probe, fused bucket-fill
    init_kernel<<<(NSEG + 255) / 256, 256>>>(cnt);
    probe_kernel<<<16, 256>>>((const long long*)eidx);
    fill_kernel<<<(NE + 255) / 256, 256>>>(eidx, etype, ew, cnt, list);

    // 1) gather (slot #4: profiled) + weight rounding + overflow fallback
    gather_kernel<<<(NSEG * 4 + 255) / 256, 256>>>(x, cnt, list, upd);
    round_weights_kernel<<<WTOTAL / 256, 256>>>(mlpW, wih, whh);
    fallback_kernel<<<(NE + 255) / 256, 256>>>(x, ew, upd);

    // 2) hidden = relu(update @ mlpW^T + mlpb)  — A already tf32 (CVT_A=0)
    gemm_tf32<KU, 1, 0, 1><<<dim3(MB128, DH / 64), 256>>>(
        upd, wbuf + WOFF_MLP, mlpb, hid, NN, DH);

    // 3) gi = hidden @ w_ih^T + b_ih            — A already tf32 (CVT_A=0)
    gemm_tf32<DH, 0, 0, 0><<<dim3(MB128, G3 / 64), 256>>>(
        hid, wbuf + WOFF_IH, bih, gi, NN, G3);

    // 4) gh = x @ w_hh^T + b_hh                 — A raw fp32 (CVT_A=1)
    gemm_tf32<DI, 0, 1, 0><<<dim3(MB128, G3 / 64), 256>>>(
        x, wbuf + WOFF_HH, bhh, gh, NN, G3);

    // 5) GRU gates -> out (vectorized)
    gates_kernel<<<(NN * 16 + 255) / 256, 256>>>(x, gi, gh, out);
}

// round 17
// speedup vs baseline: 1.0402x; 1.0402x over previous
#include <cuda_runtime.h>
#include <cuda_bf16.h>
#include <math.h>
#include <stdint.h>

// Problem constants (shapes fixed by the dataset)
#define NN 100000           // nodes
#define NE 1000000          // edges
#define ET 4                // edge types
#define DI 64               // input dim
#define DH 256              // hidden dim
#define KU (ET*DI)          // 256 = update row width
#define G3 (3*DI)           // 192 = gate width
#define NSEG (NN*ET)        // 400000 segments
#define CAP 16              // edges per segment capacity (one 128B line; overflow handled)

// Scratch (device globals — allocation-free)
__device__ float g_update[(size_t)NN * KU];   // 102.4 MB
__device__ float g_hidden[(size_t)NN * DH];   // 102.4 MB
__device__ float g_gi[(size_t)NN * G3];       // 76.8 MB (edge lists pre-GEMM2: 400k*16*8B = 51.2MB)
__device__ float g_gh[(size_t)NN * G3];       // 76.8 MB (first 1.6MB = counts)
__device__ int   g_src[NE];                   // overflow-only
__device__ int   g_dst[NE];                   // overflow-only
__device__ int   g_typ[NE];                   // overflow-only
__device__ int   g_pos[NE];                   // overflow-only (read iff g_ovf)
__device__ int   g_is_i32;                    // 1 => edge arrays are int32
__device__ int   g_ovf;                       // 1 => at least one overflow edge

// Pre-rounded (tf32) weight copies
#define WOFF_MLP 0
#define WOFF_IH  (DH*KU)                   // 65536
#define WOFF_HH  (WOFF_IH + G3*DH)         // 114688
#define WTOTAL   (WOFF_HH + G3*DI)         // 126976
__device__ float g_wbuf[WTOTAL];

// ---------------------------------------------------------------------------
// tf32 helpers
// ---------------------------------------------------------------------------
__device__ __forceinline__ uint32_t to_tf32(float v) {
    uint32_t u;
    asm("cvt.rna.tf32.f32 %0, %1;" : "=r"(u) : "f"(v));
    return u;
}

__device__ __forceinline__ uint32_t smem_u32(const void* p) {
    return (uint32_t)__cvta_generic_to_shared(p);
}

// ---------------------------------------------------------------------------
// init: zero the segment counters + reset flags
// ---------------------------------------------------------------------------
__global__ void init_kernel(int* __restrict__ cnt) {
    int i = blockIdx.x * blockDim.x + threadIdx.x;
    if (i < NSEG) cnt[i] = 0;
    if (i == 0) { g_is_i32 = 0; g_ovf = 0; }
}

__global__ void probe_kernel(const long long* __restrict__ eidx) {
    int i = blockIdx.x * blockDim.x + threadIdx.x;   // 4096 probes
    long long v = eidx[i];
    if (v < 0 || v >= (long long)NN) atomicExch(&g_is_i32, 1);
}

// ---------------------------------------------------------------------------
// Fused convert+fill, 2 edges per thread (two independent load->atomic chains
// double memory-level parallelism on this latency-bound kernel).
// ---------------------------------------------------------------------------
__device__ __forceinline__ void fill_one(int e,
                                         const void* __restrict__ eidx,
                                         const void* __restrict__ etype,
                                         const float* __restrict__ ew,
                                         int* __restrict__ cnt,
                                         unsigned long long* __restrict__ list,
                                         int is32) {
    if (e >= NE) return;
    int src, dst, t;
    if (is32) {
        const int* p = (const int*)eidx;
        src = p[e];
        dst = p[NE + e];
        t   = ((const int*)etype)[e];
    } else {
        const long long* p = (const long long*)eidx;
        src = (int)p[e];
        dst = (int)p[NE + e];
        t   = (int)((const long long*)etype)[e];
    }
    if ((unsigned)dst >= NN || (unsigned)t >= ET || (unsigned)src >= NN) return;
    int slot = dst * ET + t;
    int pos = atomicAdd(&cnt[slot], 1);
    if (pos < CAP) {
        unsigned long long pk =
            (unsigned long long)(unsigned)src |
            ((unsigned long long)__float_as_uint(ew[e]) << 32);
        list[(size_t)slot * CAP + pos] = pk;
    } else {                          // overflow: record for fallback
        g_pos[e] = pos;
        g_src[e] = src;
        g_dst[e] = dst;
        g_typ[e] = t;
        atomicExch(&g_ovf, 1);
    }
}

__global__ void fill_kernel(const void* __restrict__ eidx,
                            const void* __restrict__ etype,
                            const float* __restrict__ ew,
                            int* __restrict__ cnt,
                            unsigned long long* __restrict__ list) {
    int i = blockIdx.x * blockDim.x + threadIdx.x;
    int is32 = g_is_i32;
    fill_one(2 * i,     eidx, etype, ew, cnt, list, is32);
    fill_one(2 * i + 1, eidx, etype, ew, cnt, list, is32);
}

__global__ void round_weights_kernel(const float* __restrict__ mlpW,
                                     const float* __restrict__ wih,
                                     const float* __restrict__ whh) {
    int i = blockIdx.x * blockDim.x + threadIdx.x;
    if (i >= WTOTAL) return;
    float v;
    if (i < WOFF_IH)       v = mlpW[i];
    else if (i < WOFF_HH)  v = wih[i - WOFF_IH];
    else                   v = whh[i - WOFF_HH];
    g_wbuf[i] = __uint_as_float(to_tf32(v));
}

// ---------------------------------------------------------------------------
// gather (R15 known-good mapping): 8 threads/segment, each owns 8 floats.
// List entries loaded once per group and broadcast via shfl(width=8); the
// second list line is loaded only when n > 8 (P ~ 0.1%), halving list traffic.
// Output rounded rna->tf32 so GEMM1 skips its A-side cvt.
// ---------------------------------------------------------------------------
__global__ void gather_kernel(const float* __restrict__ x,
                              const int* __restrict__ cnt,
                              const unsigned long long* __restrict__ list,
                              float* __restrict__ upd) {
    int i = blockIdx.x * blockDim.x + threadIdx.x;   // NSEG*8 work items
    int seg = i >> 3;
    int t8  = i & 7;
    int c   = t8 * 8;          // float offset within the 64-wide row
    if (seg >= NSEG) return;
    int n = cnt[seg];
    if (n > CAP) n = CAP;
    const unsigned long long* lp = list + (size_t)seg * CAP;
    unsigned long long e0 = lp[t8];
    unsigned long long e1 = 0;
    if (n > 8) e1 = lp[t8 + 8];        // uniform across the group: no divergence
    float4 a0 = make_float4(0.f, 0.f, 0.f, 0.f);
    float4 a1 = make_float4(0.f, 0.f, 0.f, 0.f);
    for (int j = 0; j < n; j++) {
        unsigned long long pk = (j < 8)
            ? __shfl_sync(0xffffffffu, e0, j, 8)
            : __shfl_sync(0xffffffffu, e1, j - 8, 8);
        int   src = (int)(unsigned)(pk & 0xffffffffull);
        float w   = __uint_as_float((uint32_t)(pk >> 32));
        if ((unsigned)src < NN) {
            const float* xr = x + (size_t)src * DI + c;
            float4 v0 = *(const float4*)(xr);
            float4 v1 = *(const float4*)(xr + 4);
            a0.x += w * v0.x; a0.y += w * v0.y; a0.z += w * v0.z; a0.w += w * v0.w;
            a1.x += w * v1.x; a1.y += w * v1.y; a1.z += w * v1.z; a1.w += w * v1.w;
        }
    }
    a0.x = __uint_as_float(to_tf32(a0.x));
    a0.y = __uint_as_float(to_tf32(a0.y));
    a0.z = __uint_as_float(to_tf32(a0.z));
    a0.w = __uint_as_float(to_tf32(a0.w));
    a1.x = __uint_as_float(to_tf32(a1.x));
    a1.y = __uint_as_float(to_tf32(a1.y));
    a1.z = __uint_as_float(to_tf32(a1.z));
    a1.w = __uint_as_float(to_tf32(a1.w));
    float* ur = upd + (size_t)seg * DI + c;
    *(float4*)(ur)     = a0;
    *(float4*)(ur + 4) = a1;
}

// Overflow edges (essentially never) — whole grid exits on one flag load.
__global__ void fallback_kernel(const float* __restrict__ x,
                                const float* __restrict__ ew,
                                float* __restrict__ upd) {
    if (!g_ovf) return;
    int e = blockIdx.x * blockDim.x + threadIdx.x;
    if (e >= NE) return;
    if (g_pos[e] < CAP) return;
    int src = g_src[e];
    int dst = g_dst[e];
    int t   = g_typ[e];
    if ((unsigned)src >= NN || (unsigned)dst >= NN || (unsigned)t >= ET) return;
    float w = ew[e];
    float* drow = upd + ((size_t)dst * ET + t) * DI;
    for (int c = 0; c < 16; c++) {
        float4 v = *(const float4*)(x + (size_t)src * DI + c * 4);
        float p0 = __uint_as_float(to_tf32(w * v.x));
        float p1 = __uint_as_float(to_tf32(w * v.y));
        float p2 = __uint_as_float(to_tf32(w * v.z));
        float p3 = __uint_as_float(to_tf32(w * v.w));
        asm volatile("red.global.add.v4.f32 [%0], {%1,%2,%3,%4};"
                     :: "l"(drow + c * 4), "f"(p0), "f"(p1), "f"(p2), "f"(p3)
                     : "memory");
    }
}

// ---------------------------------------------------------------------------
// TF32 mma.sync GEMM, BK=32, 3-stage cp.async (known good)
// ---------------------------------------------------------------------------
#define MMA_TF32(d, a, b0, b1)                                                 \
    asm volatile(                                                              \
        "mma.sync.aligned.m16n8k8.row.col.f32.tf32.tf32.f32 "                  \
        "{%0,%1,%2,%3},{%4,%5,%6,%7},{%8,%9},{%0,%1,%2,%3};"                   \
        : "+f"((d)[0]), "+f"((d)[1]), "+f"((d)[2]), "+f"((d)[3])               \
        : "r"((a)[0]), "r"((a)[1]), "r"((a)[2]), "r"((a)[3]),                  \
          "r"(b0), "r"(b1))

template<int K, int RELU, int CVT_A, int CVT_OUT>
__global__ void __launch_bounds__(256) gemm_tf32(const float* __restrict__ A,
                                                 const float* __restrict__ B,
                                                 const float* __restrict__ bias,
                                                 float* __restrict__ C,
                                                 int M, int N) {
    __shared__ float As[3][128][36];
    __shared__ float Bs[3][64][36];

    const int tid  = threadIdx.x;
    const int lane = tid & 31;
    const int w    = tid >> 5;
    const int wm   = (w & 3) * 32;
    const int wn   = (w >> 2) * 32;
    const int m0   = blockIdx.x * 128;
    const int n0   = blockIdx.y * 64;

    const int lrow = tid >> 3;
    const int lcol = (tid & 7) * 4;

    const int niter = K / 32;

    auto issue_tile = [&](int it, int s) {
        int k0 = it * 32;
#pragma unroll
        for (int p = 0; p < 4; p++) {
            int r  = p * 32 + lrow;
            int gm = m0 + r;
            const float* src = A + (size_t)gm * K + k0 + lcol;
            uint32_t dst = smem_u32(&As[s][r][lcol]);
            int sz = (gm < M) ? 16 : 0;
            asm volatile("cp.async.cg.shared.global [%0], [%1], 16, %2;"
                         :: "r"(dst), "l"(src), "r"(sz));
        }
#pragma unroll
        for (int p = 0; p < 2; p++) {
            int r = p * 32 + lrow;
            const float* src = B + (size_t)(n0 + r) * K + k0 + lcol;
            uint32_t dst = smem_u32(&Bs[s][r][lcol]);
            asm volatile("cp.async.cg.shared.global [%0], [%1], 16;"
                         :: "r"(dst), "l"(src));
        }
    };

    float acc[2][4][4];
#pragma unroll
    for (int mt = 0; mt < 2; mt++)
#pragma unroll
        for (int nt = 0; nt < 4; nt++)
#pragma unroll
            for (int j = 0; j < 4; j++) acc[mt][nt][j] = 0.f;

    issue_tile(0, 0);
    asm volatile("cp.async.commit_group;");
    if (niter > 1) issue_tile(1, 1);
    asm volatile("cp.async.commit_group;");

    int s = 0, s2 = 2;
    for (int i = 0; i < niter; i++) {
        asm volatile("cp.async.wait_group 1;");
        __syncthreads();

        if (i + 2 < niter) issue_tile(i + 2, s2);
        asm volatile("cp.async.commit_group;");

#pragma unroll
        for (int ks = 0; ks < 32; ks += 8) {
            uint32_t af[2][4];
#pragma unroll
            for (int mt = 0; mt < 2; mt++) {
                int r = wm + mt * 16 + (lane >> 2);
                int c = ks + (lane & 3);
                if (CVT_A) {
                    af[mt][0] = to_tf32(As[s][r][c]);
                    af[mt][1] = to_tf32(As[s][r + 8][c]);
                    af[mt][2] = to_tf32(As[s][r][c + 4]);
                    af[mt][3] = to_tf32(As[s][r + 8][c + 4]);
                } else {
                    af[mt][0] = __float_as_uint(As[s][r][c]);
                    af[mt][1] = __float_as_uint(As[s][r + 8][c]);
                    af[mt][2] = __float_as_uint(As[s][r][c + 4]);
                    af[mt][3] = __float_as_uint(As[s][r + 8][c + 4]);
                }
            }
#pragma unroll
            for (int nt = 0; nt < 4; nt++) {
                int cn = wn + nt * 8 + (lane >> 2);
                int ck = ks + (lane & 3);
                uint32_t b0 = __float_as_uint(Bs[s][cn][ck]);
                uint32_t b1 = __float_as_uint(Bs[s][cn][ck + 4]);
                MMA_TF32(acc[0][nt], af[0], b0, b1);
                MMA_TF32(acc[1][nt], af[1], b0, b1);
            }
        }
        s  = (s  == 2) ? 0 : s  + 1;
        s2 = (s2 == 2) ? 0 : s2 + 1;
    }

#pragma unroll
    for (int mt = 0; mt < 2; mt++) {
#pragma unroll
        for (int nt = 0; nt < 4; nt++) {
            int row = m0 + wm + mt * 16 + (lane >> 2);
            int col = n0 + wn + nt * 8 + 2 * (lane & 3);
            float b0v = bias[col];
            float b1v = bias[col + 1];
            float v0 = acc[mt][nt][0] + b0v;
            float v1 = acc[mt][nt][1] + b1v;
            float v2 = acc[mt][nt][2] + b0v;
            float v3 = acc[mt][nt][3] + b1v;
            if (RELU) {
                v0 = fmaxf(v0, 0.f); v1 = fmaxf(v1, 0.f);
                v2 = fmaxf(v2, 0.f); v3 = fmaxf(v3, 0.f);
            }
            if (CVT_OUT) {
                v0 = __uint_as_float(to_tf32(v0));
                v1 = __uint_as_float(to_tf32(v1));
                v2 = __uint_as_float(to_tf32(v2));
                v3 = __uint_as_float(to_tf32(v3));
            }
            if (row < M)
                *(float2*)(C + (size_t)row * N + col) = make_float2(v0, v1);
            if (row + 8 < M)
                *(float2*)(C + (size_t)(row + 8) * N + col) = make_float2(v2, v3);
        }
    }
}

// ---------------------------------------------------------------------------
// GRU gate epilogue, vectorized (known good)
// ---------------------------------------------------------------------------
__global__ void gates_kernel(const float* __restrict__ x,
                             const float* __restrict__ gi,
                             const float* __restrict__ gh,
                             float* __restrict__ out) {
    int i = blockIdx.x * blockDim.x + threadIdx.x;   // NN*16 work items
    if (i >= NN * 16) return;
    int m = i >> 4;
    int c = (i & 15) * 4;
    const float* gim = gi + (size_t)m * G3;
    const float* ghm = gh + (size_t)m * G3;
    float4 ir  = *(const float4*)(gim + c);
    float4 iz  = *(const float4*)(gim + 64 + c);
    float4 in_ = *(const float4*)(gim + 128 + c);
    float4 hr  = *(const float4*)(ghm + c);
    float4 hz  = *(const float4*)(ghm + 64 + c);
    float4 hn  = *(const float4*)(ghm + 128 + c);
    float4 hv  = *(const float4*)(x + (size_t)m * DI + c);
    float4 o;
    {
        float r = 1.f / (1.f + expf(-(ir.x + hr.x)));
        float z = 1.f / (1.f + expf(-(iz.x + hz.x)));
        float n = tanhf(in_.x + r * hn.x);
        o.x = (1.f - z) * n + z * hv.x;
    }
    {
        float r = 1.f / (1.f + expf(-(ir.y + hr.y)));
        float z = 1.f / (1.f + expf(-(iz.y + hz.y)));
        float n = tanhf(in_.y + r * hn.y);
        o.y = (1.f - z) * n + z * hv.y;
    }
    {
        float r = 1.f / (1.f + expf(-(ir.z + hr.z)));
        float z = 1.f / (1.f + expf(-(iz.z + hz.z)));
        float n = tanhf(in_.z + r * hn.z);
        o.z = (1.f - z) * n + z * hv.z;
    }
    {
        float r = 1.f / (1.f + expf(-(ir.w + hr.w)));
        float z = 1.f / (1.f + expf(-(iz.w + hz.w)));
        float n = tanhf(in_.w + r * hn.w);
        o.w = (1.f - z) * n + z * hv.w;
    }
    *(float4*)(out + (size_t)m * DI + c) = o;
}

// ---------------------------------------------------------------------------
// Launch
// ---------------------------------------------------------------------------
extern "C" void kernel_launch(void* const* d_in, const int* in_sizes, int n_in,
                              void* d_out, int out_size) {
    const float* x     = (const float*)d_in[0];      // [NN, 64]
    const void*  eidx  = d_in[1];                    // [2, NE] int32 or int64
    const void*  etype = d_in[2];                    // [NE]
    const float* ew    = (const float*)d_in[3];      // [NE]
    const float* mlpW  = (const float*)d_in[4];      // [256, 256]
    const float* mlpb  = (const float*)d_in[5];      // [256]
    const float* wih   = (const float*)d_in[6];      // [192, 256]
    const float* whh   = (const float*)d_in[7];      // [192, 64]
    const float* bih   = (const float*)d_in[8];      // [192]
    const float* bhh   = (const float*)d_in[9];      // [192]
    float*       out   = (float*)d_out;              // [NN, 64]

    float *upd, *hid, *gi, *gh, *wbuf;
    cudaGetSymbolAddress((void**)&upd, g_update);
    cudaGetSymbolAddress((void**)&hid, g_hidden);
    cudaGetSymbolAddress((void**)&gi,  g_gi);
    cudaGetSymbolAddress((void**)&gh,  g_gh);
    cudaGetSymbolAddress((void**)&wbuf, g_wbuf);

    int* cnt = (int*)gh;                                // 1.6MB of g_gh
    unsigned long long* list = (unsigned long long*)gi; // 51.2MB of g_gi

    const int MB128 = (NN + 127) / 128;   // 782

    // 0) init counters+flags, dtype probe, fused bucket-fill (2 edges/thread)
    init_kernel<<<(NSEG + 255) / 256, 256>>>(cnt);
    probe_kernel<<<16, 256>>>((const long long*)eidx);
    fill_kernel<<<(NE / 2 + 255) / 256, 256>>>(eidx, etype, ew, cnt, list);

    // 1) gather (slot #4: profiled) + weight rounding + overflow fallback
    gather_kernel<<<(NSEG * 8 + 255) / 256, 256>>>(x, cnt, list, upd);
    round_weights_kernel<<<WTOTAL / 256, 256>>>(mlpW, wih, whh);
    fallback_kernel<<<(NE + 255) / 256, 256>>>(x, ew, upd);

    // 2) hidden = relu(update @ mlpW^T + mlpb)  — A already tf32 (CVT_A=0)
    gemm_tf32<KU, 1, 0, 1><<<dim3(MB128, DH / 64), 256>>>(
        upd, wbuf + WOFF_MLP, mlpb, hid, NN, DH);

    // 3) gi = hidden @ w_ih^T + b_ih            — A already tf32 (CVT_A=0)
    gemm_tf32<DH, 0, 0, 0><<<dim3(MB128, G3 / 64), 256>>>(
        hid, wbuf + WOFF_IH, bih, gi, NN, G3);

    // 4) gh = x @ w_hh^T + b_hh                 — A raw fp32 (CVT_A=1)
    gemm_tf32<DI, 0, 1, 0><<<dim3(MB128, G3 / 64), 256>>>(
        x, wbuf + WOFF_HH, bhh, gh, NN, G3);

    // 5) GRU gates -> out (vectorized)
    gates_kernel<<<(NN * 16 + 255) / 256, 256>>>(x, gi, gh, out);
}